// round 10
// baseline (speedup 1.0000x reference)
#include <cuda_runtime.h>
#include <cstdint>

#define BB 128
#define TT 2048
#define DD 64
#define HH 128
#define OO 32
#define GG 8            // batch elements per scan CTA (= mma N)
#define NCTA (BB / GG)  // 16

typedef unsigned long long ull;

// Scratch (allocation-free rule: __device__ globals)
__device__ float g_xp0[(size_t)BB * TT * HH];  // layer0 input projection
__device__ float g_h1[(size_t)BB * TT * HH];   // layer1 hidden states

// ---------------------------------------------------------------------------
// short tanh: no clamp needed (ex2(+inf)=inf -> rcp=0 -> t=1). ~1e-6 rel err.
__device__ __forceinline__ float fast_tanh(float x) {
    float ax = fabsf(x);
    float y  = ax * 2.8853900817779268f;   // 2*log2(e)
    float e;  asm("ex2.approx.f32 %0, %1;" : "=f"(e) : "f"(y));
    float d  = e + 1.0f;
    float r;  asm("rcp.approx.f32 %0, %1;" : "=f"(r) : "f"(d));
    float t  = fmaf(-2.0f, r, 1.0f);
    return copysignf(t, x);
}

__device__ __forceinline__ unsigned f2tf32(float x) {
    unsigned u;
    asm("cvt.rna.tf32.f32 %0, %1;" : "=r"(u) : "f"(x));
    return u;
}

#define MMA_TF32(d0, d1, d2, d3, a0, a1, a2, a3, b0, b1)                     \
    asm volatile(                                                            \
        "mma.sync.aligned.m16n8k8.row.col.f32.tf32.tf32.f32 "               \
        "{%0,%1,%2,%3}, {%4,%5,%6,%7}, {%8,%9}, {%0,%1,%2,%3};"             \
        : "+f"(d0), "+f"(d1), "+f"(d2), "+f"(d3)                             \
        : "r"(a0), "r"(a1), "r"(a2), "r"(a3), "r"(b0), "r"(b1))

// ---------------------------------------------------------------------------
// Kernel 1: xp0 = x @ Wih0^T + biases. At scalar-FFMA roofline — unchanged.
#define XPAD 132
__global__ void __launch_bounds__(256)
xproj_kernel(const float* __restrict__ x, const float* __restrict__ Wih0,
             const float* __restrict__ bih0, const float* __restrict__ bhh0) {
    extern __shared__ float sm[];
    float* xsT = sm;
    float* wsT = sm + 64 * XPAD;
    int tid  = threadIdx.x;
    int row0 = blockIdx.x * 128;

    const float4* xg = (const float4*)(x + (size_t)row0 * DD);
#pragma unroll
    for (int j = 0; j < 8; j++) {
        int idx = tid + 256 * j;
        float4 v = xg[idx];
        int r = idx >> 4, d4 = (idx & 15) << 2;
        xsT[(d4 + 0) * XPAD + r] = v.x;
        xsT[(d4 + 1) * XPAD + r] = v.y;
        xsT[(d4 + 2) * XPAD + r] = v.z;
        xsT[(d4 + 3) * XPAD + r] = v.w;
    }
    const float4* wg = (const float4*)Wih0;
#pragma unroll
    for (int j = 0; j < 8; j++) {
        int idx = tid + 256 * j;
        float4 v = wg[idx];
        int h = idx >> 4, d4 = (idx & 15) << 2;
        wsT[(d4 + 0) * XPAD + h] = v.x;
        wsT[(d4 + 1) * XPAD + h] = v.y;
        wsT[(d4 + 2) * XPAD + h] = v.z;
        wsT[(d4 + 3) * XPAD + h] = v.w;
    }

    int tx = tid & 15, ty = tid >> 4;
    int c0 = tx * 8, r0 = ty * 8;
    float acc[8][8];
#pragma unroll
    for (int j = 0; j < 8; j++) {
        float bb = bih0[c0 + j] + bhh0[c0 + j];
#pragma unroll
        for (int i = 0; i < 8; i++) acc[i][j] = bb;
    }
    __syncthreads();

#pragma unroll 8
    for (int k = 0; k < 64; k++) {
        float4 a0 = *(const float4*)&xsT[k * XPAD + r0];
        float4 a1 = *(const float4*)&xsT[k * XPAD + r0 + 4];
        float4 b0 = *(const float4*)&wsT[k * XPAD + c0];
        float4 b1 = *(const float4*)&wsT[k * XPAD + c0 + 4];
        float av[8] = {a0.x, a0.y, a0.z, a0.w, a1.x, a1.y, a1.z, a1.w};
        float bv[8] = {b0.x, b0.y, b0.z, b0.w, b1.x, b1.y, b1.z, b1.w};
#pragma unroll
        for (int i = 0; i < 8; i++)
#pragma unroll
            for (int j = 0; j < 8; j++)
                acc[i][j] = fmaf(av[i], bv[j], acc[i][j]);
    }

    float* og = g_xp0 + (size_t)row0 * HH;
#pragma unroll
    for (int i = 0; i < 8; i++) {
        *(float4*)&og[(size_t)(r0 + i) * HH + c0] =
            make_float4(acc[i][0], acc[i][1], acc[i][2], acc[i][3]);
        *(float4*)&og[(size_t)(r0 + i) * HH + c0 + 4] =
            make_float4(acc[i][4], acc[i][5], acc[i][6], acc[i][7]);
    }
}

// ---------------------------------------------------------------------------
// Kernel 2: TENSOR-CORE scan via legacy mma.sync (m16n8k8 tf32).
// 16 CTAs x 8 batch elements, 384 threads = 12 warps:
//   warps 0-3: g0 = Whh0 (layer0 rec), 4-7: g1 = Wih1, 8-11: g2 = Whh1.
// Each warp owns 2 M-tiles (16 rows each) of its matrix: A-frags persistent
// in registers (128 regs). B = h vectors in smem [128][8] (double-buffered),
// R3 dataflow: step s: g0 -> h0[s], g1 -> p1[s-1], g2 -> h1[s-2].
// One __syncthreads per step. h published in smem pre-rounded to tf32.
__global__ void __launch_bounds__(384, 1)
scan_mma_kernel(const float* __restrict__ Whh0, const float* __restrict__ Wih1,
                const float* __restrict__ Whh1, const float* __restrict__ bih1,
                const float* __restrict__ bhh1, const int* __restrict__ lengths) {
    __shared__ __align__(16) float h0s[2][HH][GG];
    __shared__ __align__(16) float h1s[2][HH][GG];
    __shared__ __align__(16) float p1s[2][HH][GG];

    int tid  = threadIdx.x;
    int wid  = tid >> 5;
    int lane = tid & 31;
    int gid  = lane >> 2;     // 0..7
    int tig  = lane & 3;      // 0..3
    int b0   = blockIdx.x * GG;
    int L    = lengths[b0];   // group max (lengths sorted descending)

    int g   = wid >> 2;       // 0,1,2
    int mt0 = (wid & 3) * 2;  // this warp's two M-tiles

    const float* W = (g == 0) ? Whh0 : ((g == 1) ? Wih1 : Whh1);

    // Persistent A fragments: wa[p][kt][0..3] (tf32 bits), 128 regs
    unsigned wa[2][16][4];
#pragma unroll
    for (int p = 0; p < 2; p++) {
        int r0 = (mt0 + p) * 16 + gid;
        int r1 = r0 + 8;
#pragma unroll
        for (int kt = 0; kt < 16; kt++) {
            int c = kt * 8 + tig;
            wa[p][kt][0] = f2tf32(W[r0 * HH + c]);
            wa[p][kt][1] = f2tf32(W[r1 * HH + c]);
            wa[p][kt][2] = f2tf32(W[r0 * HH + c + 4]);
            wa[p][kt][3] = f2tf32(W[r1 * HH + c + 4]);
        }
    }

    // Epilogue coords: D cols n0,n0+1; rows r0p, r0p+8 per pair
    int n0 = 2 * tig;

    // Shared per-group state (register-union friendly):
    //   g0: gbase=xp slab, goff[8]=elem offsets, gval[8]=prefetched xp
    //   g1: gval[0..3] = bias per (pair,row-half)
    //   g2: gbase=h1 slab, goff[8]=elem offsets
    float* gbase = nullptr;
    unsigned goff[8];
    float gval[8];
#pragma unroll
    for (int i = 0; i < 8; i++) { goff[i] = 0; gval[i] = 0.f; }

    if (g == 0) gbase = g_xp0 + (size_t)b0 * TT * HH;
    if (g == 2) gbase = g_h1  + (size_t)b0 * TT * HH;

    if (g != 1) {
#pragma unroll
        for (int p = 0; p < 2; p++) {
            int r0 = (mt0 + p) * 16 + gid;
            goff[p * 4 + 0] = (unsigned)((n0 + 0) * TT * HH + r0);
            goff[p * 4 + 1] = (unsigned)((n0 + 1) * TT * HH + r0);
            goff[p * 4 + 2] = (unsigned)((n0 + 0) * TT * HH + r0 + 8);
            goff[p * 4 + 3] = (unsigned)((n0 + 1) * TT * HH + r0 + 8);
        }
        if (g == 0) {
#pragma unroll
            for (int i = 0; i < 8; i++) gval[i] = __ldg(gbase + goff[i]); // xp[0]
        }
    } else {
#pragma unroll
        for (int p = 0; p < 2; p++) {
            int r0 = (mt0 + p) * 16 + gid;
            gval[2 * p + 0] = bih1[r0] + bhh1[r0];
            gval[2 * p + 1] = bih1[r0 + 8] + bhh1[r0 + 8];
        }
    }

    // Zero both buffers of h0s/h1s (value -1 state + garbage-proof mma input)
    {
        float* z0 = &h0s[0][0][0];
        float* z1 = &h1s[0][0][0];
        for (int i = tid; i < 2 * HH * GG; i += 384) { z0[i] = 0.f; z1[i] = 0.f; }
    }
    __syncthreads();

    int spad = ((L + 2) + 1) & ~1;
    for (int s0 = 0; s0 < spad; s0 += 2) {
#pragma unroll
        for (int u = 0; u < 2; u++) {
            int s  = s0 + u;
            int pa = u, pb = u ^ 1;
            const float (*S)[GG] = (g == 2) ? h1s[pb] : h0s[pb];

#pragma unroll
            for (int p = 0; p < 2; p++) {
                int r0 = (mt0 + p) * 16 + gid;
                int r1 = r0 + 8;
                float d0 = 0.f, d1 = 0.f, d2 = 0.f, d3 = 0.f;
#pragma unroll
                for (int kt = 0; kt < 16; kt++) {
                    unsigned bb0 = __float_as_uint(S[kt * 8 + tig][gid]);
                    unsigned bb1 = __float_as_uint(S[kt * 8 + 4 + tig][gid]);
                    MMA_TF32(d0, d1, d2, d3,
                             wa[p][kt][0], wa[p][kt][1], wa[p][kt][2], wa[p][kt][3],
                             bb0, bb1);
                }
                if (g == 0) {
                    float v0 = fast_tanh(d0 + gval[p * 4 + 0]);
                    float v1 = fast_tanh(d1 + gval[p * 4 + 1]);
                    float v2 = fast_tanh(d2 + gval[p * 4 + 2]);
                    float v3 = fast_tanh(d3 + gval[p * 4 + 3]);
                    *(float2*)&h0s[pa][r0][n0] =
                        make_float2(__uint_as_float(f2tf32(v0)), __uint_as_float(f2tf32(v1)));
                    *(float2*)&h0s[pa][r1][n0] =
                        make_float2(__uint_as_float(f2tf32(v2)), __uint_as_float(f2tf32(v3)));
                } else if (g == 1) {
                    float ba = gval[2 * p], bb = gval[2 * p + 1];
                    *(float2*)&p1s[pb][r0][n0] = make_float2(d0 + ba, d1 + ba);
                    *(float2*)&p1s[pb][r1][n0] = make_float2(d2 + bb, d3 + bb);
                } else {
                    float2 q0 = *(const float2*)&p1s[pa][r0][n0];
                    float2 q1 = *(const float2*)&p1s[pa][r1][n0];
                    float v0 = fast_tanh(d0 + q0.x);
                    float v1 = fast_tanh(d1 + q0.y);
                    float v2 = fast_tanh(d2 + q1.x);
                    float v3 = fast_tanh(d3 + q1.y);
                    if (s >= 2) {
                        *(float2*)&h1s[pa][r0][n0] =
                            make_float2(__uint_as_float(f2tf32(v0)), __uint_as_float(f2tf32(v1)));
                        *(float2*)&h1s[pa][r1][n0] =
                            make_float2(__uint_as_float(f2tf32(v2)), __uint_as_float(f2tf32(v3)));
                        size_t toff = (size_t)(s - 2) * HH;   // s-2 <= TT-1 by spad bound
                        gbase[goff[p * 4 + 0] + toff] = v0;   // full fp32 for fc
                        gbase[goff[p * 4 + 1] + toff] = v1;
                        gbase[goff[p * 4 + 2] + toff] = v2;
                        gbase[goff[p * 4 + 3] + toff] = v3;
                    }
                }
            }
            if (g == 0) {   // prefetch xp[s+1]
                int nidx = (s + 1 > TT - 1) ? (TT - 1) : (s + 1);
                size_t toff = (size_t)nidx * HH;
#pragma unroll
                for (int i = 0; i < 8; i++)
                    gval[i] = __ldg(gbase + goff[i] + toff);
            }
            __syncthreads();
        }
    }
}

// ---------------------------------------------------------------------------
// Kernel 3: out[b,t,:] = (t < L) ? h1[b,t,:] @ W_fc^T + b_fc : b_fc
__global__ void __launch_bounds__(256)
fc_kernel(const float* __restrict__ Wfc, const float* __restrict__ bfc,
          const int* __restrict__ lengths, float* __restrict__ out) {
    __shared__ __align__(16) float wfcT[HH * 33];
    __shared__ __align__(16) float h1s[32 * HH];
    __shared__ float bfcs[OO];

    int tid  = threadIdx.x;
    int row0 = blockIdx.x * 32;      // 32 | TT -> whole block is one batch b
    int b = row0 / TT;
    int L = lengths[b];

    for (int idx = tid; idx < OO * HH; idx += 256) {
        int o = idx >> 7, k = idx & 127;
        wfcT[k * 33 + o] = Wfc[idx];
    }
    if (tid < OO) bfcs[tid] = bfc[tid];
    const float4* hg = (const float4*)(g_h1 + (size_t)row0 * HH);
#pragma unroll
    for (int j = 0; j < 4; j++)
        ((float4*)h1s)[tid + 256 * j] = hg[tid + 256 * j];
    __syncthreads();

    int o  = tid & 31;
    int rg = tid >> 5;
    int tb = row0 % TT;
#pragma unroll
    for (int i = 0; i < 4; i++) {
        int r = rg * 4 + i;
        int t = tb + r;
        float res;
        if (t < L) {
            float acc = 0.f;
#pragma unroll
            for (int k = 0; k < HH; k++)
                acc = fmaf(wfcT[k * 33 + o], h1s[r * HH + k], acc);
            res = acc + bfcs[o];
        } else {
            res = bfcs[o];
        }
        out[(size_t)(row0 + r) * OO + o] = res;
    }
}

// ---------------------------------------------------------------------------
extern "C" void kernel_launch(void* const* d_in, const int* in_sizes, int n_in,
                              void* d_out, int out_size) {
    const float* x     = (const float*)d_in[0];
    const int*   len   = (const int*)  d_in[1];
    const float* Wih0  = (const float*)d_in[2];
    const float* Whh0  = (const float*)d_in[3];
    const float* bih0  = (const float*)d_in[4];
    const float* bhh0  = (const float*)d_in[5];
    const float* Wih1  = (const float*)d_in[6];
    const float* Whh1  = (const float*)d_in[7];
    const float* bih1  = (const float*)d_in[8];
    const float* bhh1  = (const float*)d_in[9];
    const float* Wfc   = (const float*)d_in[10];
    const float* bfc   = (const float*)d_in[11];
    float* out = (float*)d_out;

    cudaFuncSetAttribute(xproj_kernel, cudaFuncAttributeMaxDynamicSharedMemorySize, 67584);
    xproj_kernel<<<(BB * TT) / 128, 256, 67584>>>(x, Wih0, bih0, bhh0);
    scan_mma_kernel<<<NCTA, 384>>>(Whh0, Wih1, Whh1, bih1, bhh1, len);
    fc_kernel<<<(BB * TT) / 32, 256>>>(Wfc, bfc, len, out);
}

// round 11
// speedup vs baseline: 1.7898x; 1.7898x over previous
#include <cuda_runtime.h>
#include <cstdint>

#define BB 128
#define TT 2048
#define DD 64
#define HH 128
#define OO 32

typedef unsigned long long ull;

// Scratch (allocation-free rule: __device__ globals)
__device__ float g_xp0[(size_t)BB * TT * HH];  // layer0 input projection
__device__ float g_h1[(size_t)BB * TT * HH];   // layer1 hidden states

// ---------------------------------------------------------------------------
// MUFU tanh: single-instruction, rel err ~5e-4 per op; recurrence is
// contractive (tf32 experiment: 1e-3/step noise -> 3.5e-4 final).
__device__ __forceinline__ float tanh_mufu(float x) {
    float t;
    asm("tanh.approx.f32 %0, %1;" : "=f"(t) : "f"(x));
    return t;
}

// 128-long dot product with c0 folded into the accumulator init.
// Weights in registers as 64 packed f32x2, vector from smem via LDS.128
// (broadcast). 2 accumulator chains. (R3-proven version.)
__device__ __forceinline__ float dot128_c0(const ull* w, const float* v, float c0) {
    ull a0, a1 = 0ull;
    asm("mov.b64 %0, {%1, %2};" : "=l"(a0) : "f"(c0), "f"(0.0f));
    const ulonglong2* v2 = (const ulonglong2*)v;
#pragma unroll
    for (int j = 0; j < 32; j++) {
        ulonglong2 p = v2[j];
        asm("fma.rn.f32x2 %0, %1, %2, %0;" : "+l"(a0) : "l"(w[2 * j]),     "l"(p.x));
        asm("fma.rn.f32x2 %0, %1, %2, %0;" : "+l"(a1) : "l"(w[2 * j + 1]), "l"(p.y));
    }
    asm("add.rn.f32x2 %0, %0, %1;" : "+l"(a0) : "l"(a1));
    float lo = __uint_as_float((unsigned)(a0 & 0xffffffffu));
    float hi = __uint_as_float((unsigned)(a0 >> 32));
    return lo + hi;
}

// ---------------------------------------------------------------------------
// Kernel 1: xp0[b,t,h] = sum_d x[b,t,d]*W_ih0[h,d] + b_ih0[h] + b_hh0[h]
// smem-tiled GEMM, 128x128 tile, K=64, 8x8 register tile — now FFMA2:
// acc pairs along h, a-scalar duplicated into both halves.
#define XPAD 132
__global__ void __launch_bounds__(256)
xproj_kernel(const float* __restrict__ x, const float* __restrict__ Wih0,
             const float* __restrict__ bih0, const float* __restrict__ bhh0) {
    extern __shared__ float sm[];
    float* xsT = sm;                 // [64][XPAD] : xsT[d][r]
    float* wsT = sm + 64 * XPAD;     // [64][XPAD] : wsT[d][h]
    int tid  = threadIdx.x;
    int row0 = blockIdx.x * 128;

    const float4* xg = (const float4*)(x + (size_t)row0 * DD);
#pragma unroll
    for (int j = 0; j < 8; j++) {
        int idx = tid + 256 * j;
        float4 v = xg[idx];
        int r = idx >> 4, d4 = (idx & 15) << 2;
        xsT[(d4 + 0) * XPAD + r] = v.x;
        xsT[(d4 + 1) * XPAD + r] = v.y;
        xsT[(d4 + 2) * XPAD + r] = v.z;
        xsT[(d4 + 3) * XPAD + r] = v.w;
    }
    const float4* wg = (const float4*)Wih0;
#pragma unroll
    for (int j = 0; j < 8; j++) {
        int idx = tid + 256 * j;
        float4 v = wg[idx];
        int h = idx >> 4, d4 = (idx & 15) << 2;
        wsT[(d4 + 0) * XPAD + h] = v.x;
        wsT[(d4 + 1) * XPAD + h] = v.y;
        wsT[(d4 + 2) * XPAD + h] = v.z;
        wsT[(d4 + 3) * XPAD + h] = v.w;
    }

    int tx = tid & 15, ty = tid >> 4;
    int c0 = tx * 8, r0 = ty * 8;
    ull acc2[8][4];                 // [row][h-pair]
#pragma unroll
    for (int j2 = 0; j2 < 4; j2++) {
        float b0 = bih0[c0 + 2 * j2]     + bhh0[c0 + 2 * j2];
        float b1 = bih0[c0 + 2 * j2 + 1] + bhh0[c0 + 2 * j2 + 1];
        ull bb;
        asm("mov.b64 %0, {%1, %2};" : "=l"(bb) : "f"(b0), "f"(b1));
#pragma unroll
        for (int i = 0; i < 8; i++) acc2[i][j2] = bb;
    }
    __syncthreads();

#pragma unroll 4
    for (int k = 0; k < 64; k++) {
        float4 a0 = *(const float4*)&xsT[k * XPAD + r0];
        float4 a1 = *(const float4*)&xsT[k * XPAD + r0 + 4];
        ulonglong2 w0 = *(const ulonglong2*)&wsT[k * XPAD + c0];
        ulonglong2 w1 = *(const ulonglong2*)&wsT[k * XPAD + c0 + 4];
        float av[8] = {a0.x, a0.y, a0.z, a0.w, a1.x, a1.y, a1.z, a1.w};
        ull bv[4]   = {w0.x, w0.y, w1.x, w1.y};
#pragma unroll
        for (int i = 0; i < 8; i++) {
            ull ap;
            asm("mov.b64 %0, {%1, %1};" : "=l"(ap) : "f"(av[i]));
#pragma unroll
            for (int j2 = 0; j2 < 4; j2++)
                asm("fma.rn.f32x2 %0, %1, %2, %0;"
                    : "+l"(acc2[i][j2]) : "l"(ap), "l"(bv[j2]));
        }
    }

    float* og = g_xp0 + (size_t)row0 * HH;
#pragma unroll
    for (int i = 0; i < 8; i++) {
        ulonglong2 o0, o1;
        o0.x = acc2[i][0]; o0.y = acc2[i][1];
        o1.x = acc2[i][2]; o1.y = acc2[i][3];
        *(ulonglong2*)&og[(size_t)(r0 + i) * HH + c0]     = o0;
        *(ulonglong2*)&og[(size_t)(r0 + i) * HH + c0 + 4] = o1;
    }
}

// ---------------------------------------------------------------------------
// Kernel 2: sequential scan — R3 structure verbatim (best known, 1316.6)
// with tanh.approx replacing the exp-chain tanh.
__global__ void __launch_bounds__(384, 1)
scan_kernel(const float* __restrict__ Whh0, const float* __restrict__ Wih1,
            const float* __restrict__ Whh1, const float* __restrict__ bih1,
            const float* __restrict__ bhh1, const int* __restrict__ lengths) {
    __shared__ __align__(16) float h0buf[2][HH];
    __shared__ __align__(16) float h1buf[2][HH];
    __shared__ __align__(16) float p1buf[2][HH];

    int b   = blockIdx.x;
    int L   = lengths[b];
    int tid = threadIdx.x;
    int grp = tid >> 7;
    int row = tid & 127;
    bool isg0 = (grp == 0), isg1 = (grp == 1), isg2 = (grp == 2);

    const float* Wrow = (isg0 ? Whh0 : (isg1 ? Wih1 : Whh1)) + (size_t)row * HH;
    ull w[64];
#pragma unroll
    for (int j = 0; j < 64; j++) w[j] = ((const ull*)Wrow)[j];

    const float* xp_base = g_xp0 + (size_t)b * TT * HH + row;
    float cinit = isg1 ? (bih1[row] + bhh1[row]) : 0.f;
    float xp[4];
#pragma unroll
    for (int i = 0; i < 4; i++) xp[i] = isg0 ? xp_base[(size_t)i * HH] : cinit;

    if (isg0) h0buf[1][row] = 0.f;   // value index -1 lives in buffer 1
    if (isg2) h1buf[1][row] = 0.f;

    const float* vrd[2];
    float*       st[2];
    const float* prd[2];
#pragma unroll
    for (int pa = 0; pa < 2; pa++) {
        int pb = pa ^ 1;
        vrd[pa] = isg2 ? h1buf[pb] : h0buf[pb];
        st[pa]  = isg0 ? &h0buf[pa][row] : (isg1 ? &p1buf[pb][row] : &h1buf[pa][row]);
        prd[pa] = &p1buf[pa][row];
    }
    float* h1out = g_h1 + (size_t)b * TT * HH + row;

    __syncthreads();

    int spad = ((L + 2) + 3) & ~3;
    for (int s0 = 0; s0 < spad; s0 += 4) {
#pragma unroll
        for (int u = 0; u < 4; u++) {
            int s  = s0 + u;
            int pa = u & 1;
            float extra = *prd[pa];               // p1 value s-2 (g2 only)
            float d   = dot128_c0(w, vrd[pa], xp[u]);
            float pre = d + (isg2 ? extra : 0.f);
            float th  = tanh_mufu(pre);
            float y   = isg1 ? pre : th;
            if (!isg2 || s >= 2) *st[pa] = y;     // predicated STS
            if (isg2 && (unsigned)(s - 2) < (unsigned)TT)
                h1out[(size_t)(s - 2) * HH] = y;  // predicated STG
            if (isg0) {                           // predicated prefetch LDG
                int nidx = s + 4; if (nidx > TT - 1) nidx = TT - 1;
                xp[u] = __ldg(&xp_base[(size_t)nidx * HH]);
            }
            __syncthreads();
        }
    }
}

// ---------------------------------------------------------------------------
// Kernel 3: out[b,t,:] = (t < L) ? h1[b,t,:] @ W_fc^T + b_fc : b_fc
// FFMA2 version: each lane owns output column o = lane, caches W_fc row o in
// 64 regs (packed pairs). Per row: h pairs via broadcast LDS.128.
// Block = 32 rows, 256 threads = 8 warps x 4 rows each.
__global__ void __launch_bounds__(256)
fc_kernel(const float* __restrict__ Wfc, const float* __restrict__ bfc,
          const int* __restrict__ lengths, float* __restrict__ out) {
    __shared__ __align__(16) float h1s[32 * HH];

    int tid  = threadIdx.x;
    int lane = tid & 31;           // output column o
    int wrp  = tid >> 5;           // 8 warps, 4 rows each
    int row0 = blockIdx.x * 32;    // 32 | TT -> whole block is one batch b
    int b = row0 / TT;
    int L = lengths[b];

    // W_fc row `lane` in registers (64 packed pairs), loaded via float4 LDG
    ull w[64];
    {
        const float4* wr = (const float4*)(Wfc + (size_t)lane * HH);
#pragma unroll
        for (int j = 0; j < 32; j++) {
            float4 v = wr[j];
            asm("mov.b64 %0, {%1, %2};" : "=l"(w[2 * j])     : "f"(v.x), "f"(v.y));
            asm("mov.b64 %0, {%1, %2};" : "=l"(w[2 * j + 1]) : "f"(v.z), "f"(v.w));
        }
    }
    float bias = bfc[lane];

    const float4* hg = (const float4*)(g_h1 + (size_t)row0 * HH);
#pragma unroll
    for (int j = 0; j < 4; j++)
        ((float4*)h1s)[tid + 256 * j] = hg[tid + 256 * j];
    __syncthreads();

    int tb = row0 % TT;
#pragma unroll
    for (int i = 0; i < 4; i++) {
        int r = wrp * 4 + i;
        int t = tb + r;
        float res = bias;
        if (t < L) {
            ull a0 = 0ull, a1 = 0ull;
            const ulonglong2* hv = (const ulonglong2*)(h1s + r * HH);
#pragma unroll
            for (int j = 0; j < 32; j++) {
                ulonglong2 p = hv[j];   // broadcast across warp
                asm("fma.rn.f32x2 %0, %1, %2, %0;" : "+l"(a0) : "l"(w[2 * j]),     "l"(p.x));
                asm("fma.rn.f32x2 %0, %1, %2, %0;" : "+l"(a1) : "l"(w[2 * j + 1]), "l"(p.y));
            }
            asm("add.rn.f32x2 %0, %0, %1;" : "+l"(a0) : "l"(a1));
            float lo = __uint_as_float((unsigned)(a0 & 0xffffffffu));
            float hi = __uint_as_float((unsigned)(a0 >> 32));
            res = (lo + hi) + bias;
        }
        out[(size_t)(row0 + r) * OO + lane] = res;
    }
}

// ---------------------------------------------------------------------------
extern "C" void kernel_launch(void* const* d_in, const int* in_sizes, int n_in,
                              void* d_out, int out_size) {
    const float* x     = (const float*)d_in[0];
    const int*   len   = (const int*)  d_in[1];
    const float* Wih0  = (const float*)d_in[2];
    const float* Whh0  = (const float*)d_in[3];
    const float* bih0  = (const float*)d_in[4];
    const float* bhh0  = (const float*)d_in[5];
    const float* Wih1  = (const float*)d_in[6];
    const float* Whh1  = (const float*)d_in[7];
    const float* bih1  = (const float*)d_in[8];
    const float* bhh1  = (const float*)d_in[9];
    const float* Wfc   = (const float*)d_in[10];
    const float* bfc   = (const float*)d_in[11];
    float* out = (float*)d_out;

    static_assert(2 * 64 * XPAD * 4 == 67584, "smem size");
    cudaFuncSetAttribute(xproj_kernel, cudaFuncAttributeMaxDynamicSharedMemorySize, 67584);
    xproj_kernel<<<(BB * TT) / 128, 256, 67584>>>(x, Wih0, bih0, bhh0);
    scan_kernel<<<BB, 384>>>(Whh0, Wih1, Whh1, bih1, bhh1, len);
    fc_kernel<<<(BB * TT) / 32, 256>>>(Wfc, bfc, len, out);
}

// round 12
// speedup vs baseline: 2.0038x; 1.1196x over previous
#include <cuda_runtime.h>
#include <cstdint>

#define BB 128
#define TT 2048
#define DD 64
#define HH 128
#define OO 32

typedef unsigned long long ull;

// Scratch (allocation-free rule: __device__ globals)
__device__ float g_xp0[(size_t)BB * TT * HH];  // layer0 input projection
__device__ float g_h1[(size_t)BB * TT * HH];   // layer1 hidden states

// ---------------------------------------------------------------------------
// MUFU tanh: single instruction; measured rel_err 5.7e-6 end-to-end (R11).
__device__ __forceinline__ float tanh_mufu(float x) {
    float t;
    asm("tanh.approx.f32 %0, %1;" : "=f"(t) : "f"(x));
    return t;
}

// 128-long dot product with c0 folded into the accumulator init.
// Weights in registers as 64 packed f32x2, vector from smem via LDS.128
// (broadcast). 2 accumulator chains. (R3-proven version.)
__device__ __forceinline__ float dot128_c0(const ull* w, const float* v, float c0) {
    ull a0, a1 = 0ull;
    asm("mov.b64 %0, {%1, %2};" : "=l"(a0) : "f"(c0), "f"(0.0f));
    const ulonglong2* v2 = (const ulonglong2*)v;
#pragma unroll
    for (int j = 0; j < 32; j++) {
        ulonglong2 p = v2[j];
        asm("fma.rn.f32x2 %0, %1, %2, %0;" : "+l"(a0) : "l"(w[2 * j]),     "l"(p.x));
        asm("fma.rn.f32x2 %0, %1, %2, %0;" : "+l"(a1) : "l"(w[2 * j + 1]), "l"(p.y));
    }
    asm("add.rn.f32x2 %0, %0, %1;" : "+l"(a0) : "l"(a1));
    float lo = __uint_as_float((unsigned)(a0 & 0xffffffffu));
    float hi = __uint_as_float((unsigned)(a0 >> 32));
    return lo + hi;
}

// ---------------------------------------------------------------------------
// Kernel 1: xp0[b,t,h] = sum_d x[b,t,d]*W_ih0[h,d] + b_ih0[h] + b_hh0[h]
// R3-proven smem-tiled GEMM (125us ~= scalar-FFMA roofline). Do not touch.
#define XPAD 132
__global__ void __launch_bounds__(256)
xproj_kernel(const float* __restrict__ x, const float* __restrict__ Wih0,
             const float* __restrict__ bih0, const float* __restrict__ bhh0) {
    extern __shared__ float sm[];
    float* xsT = sm;                 // [64][XPAD] : xsT[d][r]
    float* wsT = sm + 64 * XPAD;     // [64][XPAD] : wsT[d][h]
    int tid  = threadIdx.x;
    int row0 = blockIdx.x * 128;

    const float4* xg = (const float4*)(x + (size_t)row0 * DD);
#pragma unroll
    for (int j = 0; j < 8; j++) {
        int idx = tid + 256 * j;
        float4 v = xg[idx];
        int r = idx >> 4, d4 = (idx & 15) << 2;
        xsT[(d4 + 0) * XPAD + r] = v.x;
        xsT[(d4 + 1) * XPAD + r] = v.y;
        xsT[(d4 + 2) * XPAD + r] = v.z;
        xsT[(d4 + 3) * XPAD + r] = v.w;
    }
    const float4* wg = (const float4*)Wih0;
#pragma unroll
    for (int j = 0; j < 8; j++) {
        int idx = tid + 256 * j;
        float4 v = wg[idx];
        int h = idx >> 4, d4 = (idx & 15) << 2;
        wsT[(d4 + 0) * XPAD + h] = v.x;
        wsT[(d4 + 1) * XPAD + h] = v.y;
        wsT[(d4 + 2) * XPAD + h] = v.z;
        wsT[(d4 + 3) * XPAD + h] = v.w;
    }

    int tx = tid & 15, ty = tid >> 4;
    int c0 = tx * 8, r0 = ty * 8;
    float acc[8][8];
#pragma unroll
    for (int j = 0; j < 8; j++) {
        float bb = bih0[c0 + j] + bhh0[c0 + j];
#pragma unroll
        for (int i = 0; i < 8; i++) acc[i][j] = bb;
    }
    __syncthreads();

#pragma unroll 8
    for (int k = 0; k < 64; k++) {
        float4 a0 = *(const float4*)&xsT[k * XPAD + r0];
        float4 a1 = *(const float4*)&xsT[k * XPAD + r0 + 4];
        float4 b0 = *(const float4*)&wsT[k * XPAD + c0];
        float4 b1 = *(const float4*)&wsT[k * XPAD + c0 + 4];
        float av[8] = {a0.x, a0.y, a0.z, a0.w, a1.x, a1.y, a1.z, a1.w};
        float bv[8] = {b0.x, b0.y, b0.z, b0.w, b1.x, b1.y, b1.z, b1.w};
#pragma unroll
        for (int i = 0; i < 8; i++)
#pragma unroll
            for (int j = 0; j < 8; j++)
                acc[i][j] = fmaf(av[i], bv[j], acc[i][j]);
    }

    float* og = g_xp0 + (size_t)row0 * HH;
#pragma unroll
    for (int i = 0; i < 8; i++) {
        *(float4*)&og[(size_t)(r0 + i) * HH + c0] =
            make_float4(acc[i][0], acc[i][1], acc[i][2], acc[i][3]);
        *(float4*)&og[(size_t)(r0 + i) * HH + c0 + 4] =
            make_float4(acc[i][4], acc[i][5], acc[i][6], acc[i][7]);
    }
}

// ---------------------------------------------------------------------------
// Kernel 2: sequential scan — R3 structure verbatim (best known), with the
// ONE validated change: tanh.approx (MUFU) replacing the exp-chain tanh.
__global__ void __launch_bounds__(384, 1)
scan_kernel(const float* __restrict__ Whh0, const float* __restrict__ Wih1,
            const float* __restrict__ Whh1, const float* __restrict__ bih1,
            const float* __restrict__ bhh1, const int* __restrict__ lengths) {
    __shared__ __align__(16) float h0buf[2][HH];
    __shared__ __align__(16) float h1buf[2][HH];
    __shared__ __align__(16) float p1buf[2][HH];

    int b   = blockIdx.x;
    int L   = lengths[b];
    int tid = threadIdx.x;
    int grp = tid >> 7;
    int row = tid & 127;
    bool isg0 = (grp == 0), isg1 = (grp == 1), isg2 = (grp == 2);

    const float* Wrow = (isg0 ? Whh0 : (isg1 ? Wih1 : Whh1)) + (size_t)row * HH;
    ull w[64];
#pragma unroll
    for (int j = 0; j < 64; j++) w[j] = ((const ull*)Wrow)[j];

    const float* xp_base = g_xp0 + (size_t)b * TT * HH + row;
    float cinit = isg1 ? (bih1[row] + bhh1[row]) : 0.f;
    float xp[4];
#pragma unroll
    for (int i = 0; i < 4; i++) xp[i] = isg0 ? xp_base[(size_t)i * HH] : cinit;

    if (isg0) h0buf[1][row] = 0.f;   // value index -1 lives in buffer 1
    if (isg2) h1buf[1][row] = 0.f;

    const float* vrd[2];
    float*       st[2];
    const float* prd[2];
#pragma unroll
    for (int pa = 0; pa < 2; pa++) {
        int pb = pa ^ 1;
        vrd[pa] = isg2 ? h1buf[pb] : h0buf[pb];
        st[pa]  = isg0 ? &h0buf[pa][row] : (isg1 ? &p1buf[pb][row] : &h1buf[pa][row]);
        prd[pa] = &p1buf[pa][row];
    }
    float* h1out = g_h1 + (size_t)b * TT * HH + row;

    __syncthreads();

    int spad = ((L + 2) + 3) & ~3;
    for (int s0 = 0; s0 < spad; s0 += 4) {
#pragma unroll
        for (int u = 0; u < 4; u++) {
            int s  = s0 + u;
            int pa = u & 1;
            float extra = *prd[pa];               // p1 value s-2 (g2 only)
            float d   = dot128_c0(w, vrd[pa], xp[u]);
            float pre = d + (isg2 ? extra : 0.f);
            float th  = tanh_mufu(pre);
            float y   = isg1 ? pre : th;
            if (!isg2 || s >= 2) *st[pa] = y;     // predicated STS
            if (isg2 && (unsigned)(s - 2) < (unsigned)TT)
                h1out[(size_t)(s - 2) * HH] = y;  // predicated STG
            if (isg0) {                           // predicated prefetch LDG
                int nidx = s + 4; if (nidx > TT - 1) nidx = TT - 1;
                xp[u] = __ldg(&xp_base[(size_t)nidx * HH]);
            }
            __syncthreads();
        }
    }
}

// ---------------------------------------------------------------------------
// Kernel 3: out[b,t,:] = (t < L) ? h1[b,t,:] @ W_fc^T + b_fc : b_fc
// R3-proven smem-staged version (W_fc staged once per block).
__global__ void __launch_bounds__(256)
fc_kernel(const float* __restrict__ Wfc, const float* __restrict__ bfc,
          const int* __restrict__ lengths, float* __restrict__ out) {
    __shared__ __align__(16) float wfcT[HH * 33];
    __shared__ __align__(16) float h1s[32 * HH];
    __shared__ float bfcs[OO];

    int tid  = threadIdx.x;
    int row0 = blockIdx.x * 32;      // 32 | TT -> whole block is one batch b
    int b = row0 / TT;
    int L = lengths[b];

    for (int idx = tid; idx < OO * HH; idx += 256) {
        int o = idx >> 7, k = idx & 127;
        wfcT[k * 33 + o] = Wfc[idx];
    }
    if (tid < OO) bfcs[tid] = bfc[tid];
    const float4* hg = (const float4*)(g_h1 + (size_t)row0 * HH);
#pragma unroll
    for (int j = 0; j < 4; j++)
        ((float4*)h1s)[tid + 256 * j] = hg[tid + 256 * j];
    __syncthreads();

    int o  = tid & 31;
    int rg = tid >> 5;               // 8 groups x 4 rows
    int tb = row0 % TT;
#pragma unroll
    for (int i = 0; i < 4; i++) {
        int r = rg * 4 + i;
        int t = tb + r;
        float res;
        if (t < L) {
            float acc = 0.f;
#pragma unroll
            for (int k = 0; k < HH; k++)
                acc = fmaf(wfcT[k * 33 + o], h1s[r * HH + k], acc);
            res = acc + bfcs[o];
        } else {
            res = bfcs[o];
        }
        out[(size_t)(row0 + r) * OO + o] = res;
    }
}

// ---------------------------------------------------------------------------
extern "C" void kernel_launch(void* const* d_in, const int* in_sizes, int n_in,
                              void* d_out, int out_size) {
    const float* x     = (const float*)d_in[0];
    const int*   len   = (const int*)  d_in[1];
    const float* Wih0  = (const float*)d_in[2];
    const float* Whh0  = (const float*)d_in[3];
    const float* bih0  = (const float*)d_in[4];
    const float* bhh0  = (const float*)d_in[5];
    const float* Wih1  = (const float*)d_in[6];
    const float* Whh1  = (const float*)d_in[7];
    const float* bih1  = (const float*)d_in[8];
    const float* bhh1  = (const float*)d_in[9];
    const float* Wfc   = (const float*)d_in[10];
    const float* bfc   = (const float*)d_in[11];
    float* out = (float*)d_out;

    static_assert(2 * 64 * XPAD * 4 == 67584, "smem size");
    cudaFuncSetAttribute(xproj_kernel, cudaFuncAttributeMaxDynamicSharedMemorySize, 67584);
    xproj_kernel<<<(BB * TT) / 128, 256, 67584>>>(x, Wih0, bih0, bhh0);
    scan_kernel<<<BB, 384>>>(Whh0, Wih1, Whh1, bih1, bhh1, len);
    fc_kernel<<<(BB * TT) / 32, 256>>>(Wfc, bfc, len, out);
}

// round 13
// speedup vs baseline: 2.1728x; 1.0844x over previous
#include <cuda_runtime.h>
#include <cstdint>

#define BB 128
#define TT 2048
#define DD 64
#define HH 128
#define OO 32

typedef unsigned long long ull;

// Scratch (allocation-free rule: __device__ globals)
__device__ float g_xp0[(size_t)BB * TT * HH];  // layer0 input projection
__device__ float g_h1[(size_t)BB * TT * HH];   // layer1 hidden states
__device__ int   g_scanflag[BB];               // scan-done flags (zeroed by xproj)

// ---------------------------------------------------------------------------
// MUFU tanh: single instruction; measured rel_err 5.7e-6 end-to-end (R11/R12).
__device__ __forceinline__ float tanh_mufu(float x) {
    float t;
    asm("tanh.approx.f32 %0, %1;" : "=f"(t) : "f"(x));
    return t;
}

// 128-long dot product with c0 folded into the accumulator init.
__device__ __forceinline__ float dot128_c0(const ull* w, const float* v, float c0) {
    ull a0, a1 = 0ull;
    asm("mov.b64 %0, {%1, %2};" : "=l"(a0) : "f"(c0), "f"(0.0f));
    const ulonglong2* v2 = (const ulonglong2*)v;
#pragma unroll
    for (int j = 0; j < 32; j++) {
        ulonglong2 p = v2[j];
        asm("fma.rn.f32x2 %0, %1, %2, %0;" : "+l"(a0) : "l"(w[2 * j]),     "l"(p.x));
        asm("fma.rn.f32x2 %0, %1, %2, %0;" : "+l"(a1) : "l"(w[2 * j + 1]), "l"(p.y));
    }
    asm("add.rn.f32x2 %0, %0, %1;" : "+l"(a0) : "l"(a1));
    float lo = __uint_as_float((unsigned)(a0 & 0xffffffffu));
    float hi = __uint_as_float((unsigned)(a0 >> 32));
    return lo + hi;
}

// ---------------------------------------------------------------------------
// Kernel 1: xp0[b,t,h] = sum_d x[b,t,d]*W_ih0[h,d] + b_ih0[h] + b_hh0[h]
// R3-proven smem-tiled GEMM (125us ~= scalar-FFMA roofline). Also zeroes the
// scan-done flags (visible to kernel 2 via the kernel boundary).
#define XPAD 132
__global__ void __launch_bounds__(256)
xproj_kernel(const float* __restrict__ x, const float* __restrict__ Wih0,
             const float* __restrict__ bih0, const float* __restrict__ bhh0) {
    extern __shared__ float sm[];
    float* xsT = sm;                 // [64][XPAD] : xsT[d][r]
    float* wsT = sm + 64 * XPAD;     // [64][XPAD] : wsT[d][h]
    int tid  = threadIdx.x;
    int row0 = blockIdx.x * 128;

    if (blockIdx.x == 0 && tid < BB) g_scanflag[tid] = 0;

    const float4* xg = (const float4*)(x + (size_t)row0 * DD);
#pragma unroll
    for (int j = 0; j < 8; j++) {
        int idx = tid + 256 * j;
        float4 v = xg[idx];
        int r = idx >> 4, d4 = (idx & 15) << 2;
        xsT[(d4 + 0) * XPAD + r] = v.x;
        xsT[(d4 + 1) * XPAD + r] = v.y;
        xsT[(d4 + 2) * XPAD + r] = v.z;
        xsT[(d4 + 3) * XPAD + r] = v.w;
    }
    const float4* wg = (const float4*)Wih0;
#pragma unroll
    for (int j = 0; j < 8; j++) {
        int idx = tid + 256 * j;
        float4 v = wg[idx];
        int h = idx >> 4, d4 = (idx & 15) << 2;
        wsT[(d4 + 0) * XPAD + h] = v.x;
        wsT[(d4 + 1) * XPAD + h] = v.y;
        wsT[(d4 + 2) * XPAD + h] = v.z;
        wsT[(d4 + 3) * XPAD + h] = v.w;
    }

    int tx = tid & 15, ty = tid >> 4;
    int c0 = tx * 8, r0 = ty * 8;
    float acc[8][8];
#pragma unroll
    for (int j = 0; j < 8; j++) {
        float bb = bih0[c0 + j] + bhh0[c0 + j];
#pragma unroll
        for (int i = 0; i < 8; i++) acc[i][j] = bb;
    }
    __syncthreads();

#pragma unroll 8
    for (int k = 0; k < 64; k++) {
        float4 a0 = *(const float4*)&xsT[k * XPAD + r0];
        float4 a1 = *(const float4*)&xsT[k * XPAD + r0 + 4];
        float4 b0 = *(const float4*)&wsT[k * XPAD + c0];
        float4 b1 = *(const float4*)&wsT[k * XPAD + c0 + 4];
        float av[8] = {a0.x, a0.y, a0.z, a0.w, a1.x, a1.y, a1.z, a1.w};
        float bv[8] = {b0.x, b0.y, b0.z, b0.w, b1.x, b1.y, b1.z, b1.w};
#pragma unroll
        for (int i = 0; i < 8; i++)
#pragma unroll
            for (int j = 0; j < 8; j++)
                acc[i][j] = fmaf(av[i], bv[j], acc[i][j]);
    }

    float* og = g_xp0 + (size_t)row0 * HH;
#pragma unroll
    for (int i = 0; i < 8; i++) {
        *(float4*)&og[(size_t)(r0 + i) * HH + c0] =
            make_float4(acc[i][0], acc[i][1], acc[i][2], acc[i][3]);
        *(float4*)&og[(size_t)(r0 + i) * HH + c0 + 4] =
            make_float4(acc[i][4], acc[i][5], acc[i][6], acc[i][7]);
    }
}

// ---------------------------------------------------------------------------
// Kernel 2: MERGED scan + fc.
//   blocks 0..127            : scan role (R12 body) + release flag at end.
//   blocks 128..128+8192-1   : fc role; 64 blocks per batch in REVERSE batch
//                              order (batch 127 first = finishes first);
//                              acquire-spin on the batch's flag, then fc.
// 384 threads. Scan occupies wave 1 entirely (1 CTA/SM); freed SMs pick up
// fc blocks for just-finished batches -> fc hides under the long scans.
__global__ void __launch_bounds__(384, 1)
scanfc_kernel(const float* __restrict__ Whh0, const float* __restrict__ Wih1,
              const float* __restrict__ Whh1, const float* __restrict__ bih1,
              const float* __restrict__ bhh1, const int* __restrict__ lengths,
              const float* __restrict__ Wfc,  const float* __restrict__ bfc,
              float* __restrict__ out) {
    int tid = threadIdx.x;

    if (blockIdx.x < BB) {
        // ------------------------- scan role -------------------------
        __shared__ __align__(16) float h0buf[2][HH];
        __shared__ __align__(16) float h1buf[2][HH];
        __shared__ __align__(16) float p1buf[2][HH];

        int b   = blockIdx.x;
        int L   = lengths[b];
        int grp = tid >> 7;
        int row = tid & 127;
        bool isg0 = (grp == 0), isg1 = (grp == 1), isg2 = (grp == 2);

        const float* Wrow = (isg0 ? Whh0 : (isg1 ? Wih1 : Whh1)) + (size_t)row * HH;
        ull w[64];
#pragma unroll
        for (int j = 0; j < 64; j++) w[j] = ((const ull*)Wrow)[j];

        const float* xp_base = g_xp0 + (size_t)b * TT * HH + row;
        float cinit = isg1 ? (bih1[row] + bhh1[row]) : 0.f;
        float xp[4];
#pragma unroll
        for (int i = 0; i < 4; i++) xp[i] = isg0 ? xp_base[(size_t)i * HH] : cinit;

        if (isg0) h0buf[1][row] = 0.f;   // value index -1 lives in buffer 1
        if (isg2) h1buf[1][row] = 0.f;

        const float* vrd[2];
        float*       st[2];
        const float* prd[2];
#pragma unroll
        for (int pa = 0; pa < 2; pa++) {
            int pb = pa ^ 1;
            vrd[pa] = isg2 ? h1buf[pb] : h0buf[pb];
            st[pa]  = isg0 ? &h0buf[pa][row] : (isg1 ? &p1buf[pb][row] : &h1buf[pa][row]);
            prd[pa] = &p1buf[pa][row];
        }
        float* h1out = g_h1 + (size_t)b * TT * HH + row;

        __syncthreads();

        int spad = ((L + 2) + 3) & ~3;
        for (int s0 = 0; s0 < spad; s0 += 4) {
#pragma unroll
            for (int u = 0; u < 4; u++) {
                int s  = s0 + u;
                int pa = u & 1;
                float extra = *prd[pa];               // p1 value s-2 (g2 only)
                float d   = dot128_c0(w, vrd[pa], xp[u]);
                float pre = d + (isg2 ? extra : 0.f);
                float th  = tanh_mufu(pre);
                float y   = isg1 ? pre : th;
                if (!isg2 || s >= 2) *st[pa] = y;     // predicated STS
                if (isg2 && (unsigned)(s - 2) < (unsigned)TT)
                    h1out[(size_t)(s - 2) * HH] = y;  // predicated STG
                if (isg0) {                           // predicated prefetch LDG
                    int nidx = s + 4; if (nidx > TT - 1) nidx = TT - 1;
                    xp[u] = __ldg(&xp_base[(size_t)nidx * HH]);
                }
                __syncthreads();
            }
        }

        // publish: all h1 writes -> device scope, then release the flag
        __threadfence();
        __syncthreads();
        if (tid == 0)
            asm volatile("st.release.gpu.global.b32 [%0], %1;"
                         :: "l"(&g_scanflag[b]), "r"(1) : "memory");
    } else {
        // -------------------------- fc role --------------------------
        __shared__ __align__(16) float wfcT[HH * 33];
        __shared__ __align__(16) float h1s[32 * HH];
        __shared__ float bfcs[OO];

        int f    = blockIdx.x - BB;          // 0..8191
        int b    = (BB - 1) - (f >> 6);      // 64 blocks/batch, reverse order
        int row0 = b * TT + (f & 63) * 32;
        int L    = lengths[b];

        // stage W_fc while waiting (independent of the flag)
        for (int idx = tid; idx < OO * HH; idx += 384) {
            int o = idx >> 7, k = idx & 127;
            wfcT[k * 33 + o] = Wfc[idx];
        }
        if (tid < OO) bfcs[tid] = bfc[tid];

        if (tid == 0) {
            int v;
            while (true) {
                asm volatile("ld.acquire.gpu.global.b32 %0, [%1];"
                             : "=r"(v) : "l"(&g_scanflag[b]) : "memory");
                if (v) break;
                __nanosleep(200);
            }
        }
        __syncthreads();   // flag acquired -> h1 visible; smem staged

        const float4* hg = (const float4*)(g_h1 + (size_t)row0 * HH);
        for (int j = tid; j < 1024; j += 384)
            ((float4*)h1s)[j] = hg[j];
        __syncthreads();

        if (tid < 256) {
            int o  = tid & 31;
            int rg = tid >> 5;               // 8 groups x 4 rows
            int tb = row0 % TT;
#pragma unroll
            for (int i = 0; i < 4; i++) {
                int r = rg * 4 + i;
                int t = tb + r;
                float res;
                if (t < L) {
                    float acc = 0.f;
#pragma unroll
                    for (int k = 0; k < HH; k++)
                        acc = fmaf(wfcT[k * 33 + o], h1s[r * HH + k], acc);
                    res = acc + bfcs[o];
                } else {
                    res = bfcs[o];
                }
                out[(size_t)(row0 + r) * OO + o] = res;
            }
        }
    }
}

// ---------------------------------------------------------------------------
extern "C" void kernel_launch(void* const* d_in, const int* in_sizes, int n_in,
                              void* d_out, int out_size) {
    const float* x     = (const float*)d_in[0];
    const int*   len   = (const int*)  d_in[1];
    const float* Wih0  = (const float*)d_in[2];
    const float* Whh0  = (const float*)d_in[3];
    const float* bih0  = (const float*)d_in[4];
    const float* bhh0  = (const float*)d_in[5];
    const float* Wih1  = (const float*)d_in[6];
    const float* Whh1  = (const float*)d_in[7];
    const float* bih1  = (const float*)d_in[8];
    const float* bhh1  = (const float*)d_in[9];
    const float* Wfc   = (const float*)d_in[10];
    const float* bfc   = (const float*)d_in[11];
    float* out = (float*)d_out;

    static_assert(2 * 64 * XPAD * 4 == 67584, "smem size");
    cudaFuncSetAttribute(xproj_kernel, cudaFuncAttributeMaxDynamicSharedMemorySize, 67584);
    xproj_kernel<<<(BB * TT) / 128, 256, 67584>>>(x, Wih0, bih0, bhh0);
    scanfc_kernel<<<BB + (BB * TT) / 32, 384>>>(Whh0, Wih1, Whh1, bih1, bhh1, len,
                                                Wfc, bfc, out);
}

// round 14
// speedup vs baseline: 2.4284x; 1.1176x over previous
#include <cuda_runtime.h>
#include <cstdint>

#define BB 128
#define TT 2048
#define DD 64
#define HH 128
#define OO 32
#define NCHUNK 16            // 2048 / 128 t-chunks

typedef unsigned long long ull;

// Scratch (allocation-free rule: __device__ globals)
__device__ float g_xp0[(size_t)BB * TT * HH];  // layer0 input projection
__device__ float g_h1[(size_t)BB * TT * HH];   // layer1 hidden states
__device__ int   g_scanflag[BB];               // scan-done flags
__device__ int   g_xpflag[NCHUNK * BB];        // xp chunk-ready flags [c*BB+b]

// ---------------------------------------------------------------------------
__device__ __forceinline__ float tanh_mufu(float x) {
    float t;
    asm("tanh.approx.f32 %0, %1;" : "=f"(t) : "f"(x));
    return t;
}

__device__ __forceinline__ float dot128_c0(const ull* w, const float* v, float c0) {
    ull a0, a1 = 0ull;
    asm("mov.b64 %0, {%1, %2};" : "=l"(a0) : "f"(c0), "f"(0.0f));
    const ulonglong2* v2 = (const ulonglong2*)v;
#pragma unroll
    for (int j = 0; j < 32; j++) {
        ulonglong2 p = v2[j];
        asm("fma.rn.f32x2 %0, %1, %2, %0;" : "+l"(a0) : "l"(w[2 * j]),     "l"(p.x));
        asm("fma.rn.f32x2 %0, %1, %2, %0;" : "+l"(a1) : "l"(w[2 * j + 1]), "l"(p.y));
    }
    asm("add.rn.f32x2 %0, %0, %1;" : "+l"(a0) : "l"(a1));
    float lo = __uint_as_float((unsigned)(a0 & 0xffffffffu));
    float hi = __uint_as_float((unsigned)(a0 >> 32));
    return lo + hi;
}

__device__ __forceinline__ void spin_acq(const int* p) {
    int v;
    while (true) {
        asm volatile("ld.acquire.gpu.global.b32 %0, [%1];" : "=r"(v) : "l"(p) : "memory");
        if (v) break;
        __nanosleep(100);
    }
}

// ---------------------------------------------------------------------------
// Init: zero the handshake flags (separate launch -> ordered before main).
__global__ void init_kernel() {
    int tid = threadIdx.x;
    for (int i = tid; i < NCHUNK * BB; i += 256) g_xpflag[i] = 0;
    if (tid < BB) g_scanflag[tid] = 0;
}

// ---------------------------------------------------------------------------
// MERGED kernel: xproj + scan + fc, one launch, flag handshakes.
//   blocks [0,128)        : scan role (R12 body + xp-chunk waits)
//   blocks [128,2176)     : xproj role, f=idx-128, chunk c=f>>7, batch b=f&127
//                           (chunk-major order: chunk 0 for all batches first)
//   blocks [2176,10368)   : fc role, reverse batch order, spin on scan flag
#define XPAD 132
__global__ void __launch_bounds__(384, 1)
mega_kernel(const float* __restrict__ x,
            const float* __restrict__ Wih0, const float* __restrict__ bih0,
            const float* __restrict__ bhh0,
            const float* __restrict__ Whh0, const float* __restrict__ Wih1,
            const float* __restrict__ Whh1, const float* __restrict__ bih1,
            const float* __restrict__ bhh1, const int* __restrict__ lengths,
            const float* __restrict__ Wfc,  const float* __restrict__ bfc,
            float* __restrict__ out) {
    int tid = threadIdx.x;

    if (blockIdx.x < BB) {
        // ------------------------- scan role -------------------------
        __shared__ __align__(16) float h0buf[2][HH];
        __shared__ __align__(16) float h1buf[2][HH];
        __shared__ __align__(16) float p1buf[2][HH];

        int b   = blockIdx.x;
        int L   = lengths[b];
        int grp = tid >> 7;
        int row = tid & 127;
        bool isg0 = (grp == 0), isg1 = (grp == 1), isg2 = (grp == 2);

        const float* Wrow = (isg0 ? Whh0 : (isg1 ? Wih1 : Whh1)) + (size_t)row * HH;
        ull w[64];
#pragma unroll
        for (int j = 0; j < 64; j++) w[j] = ((const ull*)Wrow)[j];

        const float* xp_base = g_xp0 + (size_t)b * TT * HH + row;
        float cinit = isg1 ? (bih1[row] + bhh1[row]) : 0.f;

        if (isg0) spin_acq(&g_xpflag[b]);     // chunk 0 of this batch ready
        float xp[4];
#pragma unroll
        for (int i = 0; i < 4; i++) xp[i] = isg0 ? xp_base[(size_t)i * HH] : cinit;

        if (isg0) h0buf[1][row] = 0.f;        // value index -1 lives in buffer 1
        if (isg2) h1buf[1][row] = 0.f;

        const float* vrd[2];
        float*       st[2];
        const float* prd[2];
#pragma unroll
        for (int pa = 0; pa < 2; pa++) {
            int pb = pa ^ 1;
            vrd[pa] = isg2 ? h1buf[pb] : h0buf[pb];
            st[pa]  = isg0 ? &h0buf[pa][row] : (isg1 ? &p1buf[pb][row] : &h1buf[pa][row]);
            prd[pa] = &p1buf[pa][row];
        }
        float* h1out = g_h1 + (size_t)b * TT * HH + row;

        __syncthreads();

        int spad = ((L + 2) + 3) & ~3;
        for (int s0 = 0; s0 < spad; s0 += 4) {
            if (((s0 & 127) == 124) && isg0) {       // prefetch window crosses chunk
                int c = (s0 + 7) >> 7; if (c > NCHUNK - 1) c = NCHUNK - 1;
                spin_acq(&g_xpflag[c * BB + b]);
            }
#pragma unroll
            for (int u = 0; u < 4; u++) {
                int s  = s0 + u;
                int pa = u & 1;
                float extra = *prd[pa];               // p1 value s-2 (g2 only)
                float d   = dot128_c0(w, vrd[pa], xp[u]);
                float pre = d + (isg2 ? extra : 0.f);
                float th  = tanh_mufu(pre);
                float y   = isg1 ? pre : th;
                if (!isg2 || s >= 2) *st[pa] = y;     // predicated STS
                if (isg2 && (unsigned)(s - 2) < (unsigned)TT)
                    h1out[(size_t)(s - 2) * HH] = y;  // predicated STG
                if (isg0) {                           // predicated prefetch LDG
                    int nidx = s + 4; if (nidx > TT - 1) nidx = TT - 1;
                    xp[u] = __ldg(&xp_base[(size_t)nidx * HH]);
                }
                __syncthreads();
            }
        }

        __threadfence();
        __syncthreads();
        if (tid == 0)
            asm volatile("st.release.gpu.global.b32 [%0], %1;"
                         :: "l"(&g_scanflag[b]), "r"(1) : "memory");
    } else if (blockIdx.x < BB + NCHUNK * BB) {
        // ------------------------ xproj role -------------------------
        extern __shared__ float sm[];
        float* xsT = sm;                 // [64][XPAD]
        float* wsT = sm + 64 * XPAD;     // [64][XPAD]
        int f    = blockIdx.x - BB;
        int c    = f >> 7;               // t-chunk (chunk-major order)
        int b    = f & 127;
        int row0 = b * TT + c * 128;     // 128 contiguous (b,t) rows

        if (tid < 256) {
            const float4* xg = (const float4*)(x + (size_t)row0 * DD);
#pragma unroll
            for (int j = 0; j < 8; j++) {
                int idx = tid + 256 * j;
                float4 v = xg[idx];
                int r = idx >> 4, d4 = (idx & 15) << 2;
                xsT[(d4 + 0) * XPAD + r] = v.x;
                xsT[(d4 + 1) * XPAD + r] = v.y;
                xsT[(d4 + 2) * XPAD + r] = v.z;
                xsT[(d4 + 3) * XPAD + r] = v.w;
            }
            const float4* wg = (const float4*)Wih0;
#pragma unroll
            for (int j = 0; j < 8; j++) {
                int idx = tid + 256 * j;
                float4 v = wg[idx];
                int h = idx >> 4, d4 = (idx & 15) << 2;
                wsT[(d4 + 0) * XPAD + h] = v.x;
                wsT[(d4 + 1) * XPAD + h] = v.y;
                wsT[(d4 + 2) * XPAD + h] = v.z;
                wsT[(d4 + 3) * XPAD + h] = v.w;
            }
        }
        __syncthreads();

        if (tid < 256) {
            int tx = tid & 15, ty = tid >> 4;
            int c0 = tx * 8, r0 = ty * 8;
            float acc[8][8];
#pragma unroll
            for (int j = 0; j < 8; j++) {
                float bb = bih0[c0 + j] + bhh0[c0 + j];
#pragma unroll
                for (int i = 0; i < 8; i++) acc[i][j] = bb;
            }
#pragma unroll 8
            for (int k = 0; k < 64; k++) {
                float4 a0 = *(const float4*)&xsT[k * XPAD + r0];
                float4 a1 = *(const float4*)&xsT[k * XPAD + r0 + 4];
                float4 b0 = *(const float4*)&wsT[k * XPAD + c0];
                float4 b1 = *(const float4*)&wsT[k * XPAD + c0 + 4];
                float av[8] = {a0.x, a0.y, a0.z, a0.w, a1.x, a1.y, a1.z, a1.w};
                float bv[8] = {b0.x, b0.y, b0.z, b0.w, b1.x, b1.y, b1.z, b1.w};
#pragma unroll
                for (int i = 0; i < 8; i++)
#pragma unroll
                    for (int j = 0; j < 8; j++)
                        acc[i][j] = fmaf(av[i], bv[j], acc[i][j]);
            }
            float* og = g_xp0 + (size_t)row0 * HH;
#pragma unroll
            for (int i = 0; i < 8; i++) {
                *(float4*)&og[(size_t)(r0 + i) * HH + c0] =
                    make_float4(acc[i][0], acc[i][1], acc[i][2], acc[i][3]);
                *(float4*)&og[(size_t)(r0 + i) * HH + c0 + 4] =
                    make_float4(acc[i][4], acc[i][5], acc[i][6], acc[i][7]);
            }
        }
        __threadfence();
        __syncthreads();
        if (tid == 0)
            asm volatile("st.release.gpu.global.b32 [%0], %1;"
                         :: "l"(&g_xpflag[c * BB + b]), "r"(1) : "memory");
    } else {
        // -------------------------- fc role --------------------------
        __shared__ __align__(16) float wfcT[HH * 33];
        __shared__ __align__(16) float h1s[32 * HH];
        __shared__ float bfcs[OO];

        int f    = blockIdx.x - (BB + NCHUNK * BB);  // 0..8191
        int b    = (BB - 1) - (f >> 6);              // reverse batch order
        int row0 = b * TT + (f & 63) * 32;
        int L    = lengths[b];

        for (int idx = tid; idx < OO * HH; idx += 384) {
            int o = idx >> 7, k = idx & 127;
            wfcT[k * 33 + o] = Wfc[idx];
        }
        if (tid < OO) bfcs[tid] = bfc[tid];

        if (tid == 0) spin_acq(&g_scanflag[b]);
        __syncthreads();   // flag acquired -> h1 visible; smem staged

        const float4* hg = (const float4*)(g_h1 + (size_t)row0 * HH);
        for (int j = tid; j < 1024; j += 384)
            ((float4*)h1s)[j] = hg[j];
        __syncthreads();

        if (tid < 256) {
            int o  = tid & 31;
            int rg = tid >> 5;               // 8 groups x 4 rows
            int tb = row0 % TT;
#pragma unroll
            for (int i = 0; i < 4; i++) {
                int r = rg * 4 + i;
                int t = tb + r;
                float res;
                if (t < L) {
                    float acc = 0.f;
#pragma unroll
                    for (int k = 0; k < HH; k++)
                        acc = fmaf(wfcT[k * 33 + o], h1s[r * HH + k], acc);
                    res = acc + bfcs[o];
                } else {
                    res = bfcs[o];
                }
                out[(size_t)(row0 + r) * OO + o] = res;
            }
        }
    }
}

// ---------------------------------------------------------------------------
extern "C" void kernel_launch(void* const* d_in, const int* in_sizes, int n_in,
                              void* d_out, int out_size) {
    const float* x     = (const float*)d_in[0];
    const int*   len   = (const int*)  d_in[1];
    const float* Wih0  = (const float*)d_in[2];
    const float* Whh0  = (const float*)d_in[3];
    const float* bih0  = (const float*)d_in[4];
    const float* bhh0  = (const float*)d_in[5];
    const float* Wih1  = (const float*)d_in[6];
    const float* Whh1  = (const float*)d_in[7];
    const float* bih1  = (const float*)d_in[8];
    const float* bhh1  = (const float*)d_in[9];
    const float* Wfc   = (const float*)d_in[10];
    const float* bfc   = (const float*)d_in[11];
    float* out = (float*)d_out;

    init_kernel<<<1, 256>>>();

    static_assert(2 * 64 * XPAD * 4 == 67584, "smem size");
    cudaFuncSetAttribute(mega_kernel, cudaFuncAttributeMaxDynamicSharedMemorySize, 67584);
    int grid = BB + NCHUNK * BB + (BB * TT) / 32;   // 128 + 2048 + 8192
    mega_kernel<<<grid, 384, 67584>>>(x, Wih0, bih0, bhh0,
                                      Whh0, Wih1, Whh1, bih1, bhh1, len,
                                      Wfc, bfc, out);
}

// round 15
// speedup vs baseline: 2.8723x; 1.1828x over previous
#include <cuda_runtime.h>
#include <cuda_fp16.h>
#include <cstdint>

#define BB 128
#define TT 2048
#define DD 64
#define HH 128
#define OO 32
#define NCHUNK 16            // 2048 / 128 t-chunks

typedef unsigned long long ull;

// Scratch (allocation-free rule: __device__ globals)
__device__ float g_xp0[(size_t)BB * TT * HH];  // layer0 input projection
__device__ float g_h1[(size_t)BB * TT * HH];   // layer1 hidden states
__device__ int   g_scanflag[BB];               // scan-done flags
__device__ int   g_xpflag[NCHUNK * BB];        // xp chunk-ready flags [c*BB+b]

// ---------------------------------------------------------------------------
__device__ __forceinline__ float tanh_mufu(float x) {
    float t;
    asm("tanh.approx.f32 %0, %1;" : "=f"(t) : "f"(x));
    return t;
}

// 128-long fp16 dot: weights as 64 half2 in regs, vector from smem as fp16
// (16x LDS.128 broadcast). 8 independent HFMA2 chains (8-deep each),
// fp32 tree reduce. HFMA2 rt2 -> 2x fp32 MAC throughput.
__device__ __forceinline__ float dot128h(const __half2* w2, const __half* v) {
    __half2 acc[8];
#pragma unroll
    for (int i = 0; i < 8; i++) acc[i] = __float2half2_rn(0.f);
    const uint4* v4 = (const uint4*)v;          // 8 fp16 per load
#pragma unroll
    for (int j = 0; j < 16; j++) {
        uint4 p = v4[j];
        __half2 pv0 = *(const __half2*)&p.x;
        __half2 pv1 = *(const __half2*)&p.y;
        __half2 pv2 = *(const __half2*)&p.z;
        __half2 pv3 = *(const __half2*)&p.w;
        int c = (j & 1) * 4;
        acc[c + 0] = __hfma2(w2[4 * j + 0], pv0, acc[c + 0]);
        acc[c + 1] = __hfma2(w2[4 * j + 1], pv1, acc[c + 1]);
        acc[c + 2] = __hfma2(w2[4 * j + 2], pv2, acc[c + 2]);
        acc[c + 3] = __hfma2(w2[4 * j + 3], pv3, acc[c + 3]);
    }
    float2 f0 = __half22float2(acc[0]);
    float2 f1 = __half22float2(acc[1]);
    float2 f2 = __half22float2(acc[2]);
    float2 f3 = __half22float2(acc[3]);
    float2 f4 = __half22float2(acc[4]);
    float2 f5 = __half22float2(acc[5]);
    float2 f6 = __half22float2(acc[6]);
    float2 f7 = __half22float2(acc[7]);
    float p0 = (f0.x + f0.y) + (f1.x + f1.y);
    float p1 = (f2.x + f2.y) + (f3.x + f3.y);
    float p2 = (f4.x + f4.y) + (f5.x + f5.y);
    float p3 = (f6.x + f6.y) + (f7.x + f7.y);
    return (p0 + p1) + (p2 + p3);
}

__device__ __forceinline__ void spin_acq(const int* p) {
    int v;
    while (true) {
        asm volatile("ld.acquire.gpu.global.b32 %0, [%1];" : "=r"(v) : "l"(p) : "memory");
        if (v) break;
        __nanosleep(100);
    }
}

// ---------------------------------------------------------------------------
// Init: zero the handshake flags (separate launch -> ordered before main).
__global__ void init_kernel() {
    int tid = threadIdx.x;
    for (int i = tid; i < NCHUNK * BB; i += 256) g_xpflag[i] = 0;
    if (tid < BB) g_scanflag[tid] = 0;
}

// ---------------------------------------------------------------------------
// MERGED kernel: xproj + scan + fc, one launch, flag handshakes.
//   blocks [0,128)        : scan role (fp16 dots + xp-chunk waits)
//   blocks [128,2176)     : xproj role, chunk-major order
//   blocks [2176,10368)   : fc role, reverse batch order, spin on scan flag
#define XPAD 132
__global__ void __launch_bounds__(384, 1)
mega_kernel(const float* __restrict__ x,
            const float* __restrict__ Wih0, const float* __restrict__ bih0,
            const float* __restrict__ bhh0,
            const float* __restrict__ Whh0, const float* __restrict__ Wih1,
            const float* __restrict__ Whh1, const float* __restrict__ bih1,
            const float* __restrict__ bhh1, const int* __restrict__ lengths,
            const float* __restrict__ Wfc,  const float* __restrict__ bfc,
            float* __restrict__ out) {
    int tid = threadIdx.x;

    if (blockIdx.x < BB) {
        // ------------------------- scan role (fp16) -------------------------
        __shared__ __align__(16) __half h0buf[2][HH];
        __shared__ __align__(16) __half h1buf[2][HH];
        __shared__ __align__(16) float  p1buf[2][HH];

        int b   = blockIdx.x;
        int L   = lengths[b];
        int grp = tid >> 7;
        int row = tid & 127;
        bool isg0 = (grp == 0), isg1 = (grp == 1), isg2 = (grp == 2);

        const float* Wrow = (isg0 ? Whh0 : (isg1 ? Wih1 : Whh1)) + (size_t)row * HH;
        __half2 w2[64];
        {
            const float2* Wf2 = (const float2*)Wrow;
#pragma unroll
            for (int j = 0; j < 64; j++) {
                float2 t = Wf2[j];
                w2[j] = __floats2half2_rn(t.x, t.y);
            }
        }

        const float* xp_base = g_xp0 + (size_t)b * TT * HH + row;
        float cinit = isg1 ? (bih1[row] + bhh1[row]) : 0.f;

        if (isg0) spin_acq(&g_xpflag[b]);     // chunk 0 of this batch ready
        float xp[4];
#pragma unroll
        for (int i = 0; i < 4; i++) xp[i] = isg0 ? xp_base[(size_t)i * HH] : cinit;

        if (isg0) h0buf[1][row] = __float2half_rn(0.f);  // value -1 in buffer 1
        if (isg2) h1buf[1][row] = __float2half_rn(0.f);

        const __half* vrd[2];
        const float*  prd[2];
#pragma unroll
        for (int pa = 0; pa < 2; pa++) {
            int pb = pa ^ 1;
            vrd[pa] = isg2 ? h1buf[pb] : h0buf[pb];
            prd[pa] = &p1buf[pa][row];
        }
        __half* sth[2];
        float*  stf[2];
#pragma unroll
        for (int pa = 0; pa < 2; pa++) {
            int pb = pa ^ 1;
            sth[pa] = isg0 ? &h0buf[pa][row] : &h1buf[pa][row];  // g0/g2 targets
            stf[pa] = &p1buf[pb][row];                            // g1 target
        }
        float* h1out = g_h1 + (size_t)b * TT * HH + row;

        __syncthreads();

        int spad = ((L + 2) + 3) & ~3;
        for (int s0 = 0; s0 < spad; s0 += 4) {
            if (((s0 & 127) == 124) && isg0) {       // prefetch crosses chunk
                int c = (s0 + 7) >> 7; if (c > NCHUNK - 1) c = NCHUNK - 1;
                spin_acq(&g_xpflag[c * BB + b]);
            }
#pragma unroll
            for (int u = 0; u < 4; u++) {
                int s  = s0 + u;
                int pa = u & 1;
                float extra = *prd[pa];               // p1 value s-2 (g2 only)
                float d   = xp[u] + dot128h(w2, vrd[pa]);
                float pre = d + (isg2 ? extra : 0.f);
                float th  = tanh_mufu(pre);
                if (isg1) *stf[pa] = pre;             // p1 (fp32)
                else if (!isg2 || s >= 2)
                    *sth[pa] = __float2half_rn(th);   // h0/h1 (fp16)
                if (isg2 && (unsigned)(s - 2) < (unsigned)TT)
                    h1out[(size_t)(s - 2) * HH] = th; // fp32 for fc
                if (isg0) {                           // predicated prefetch LDG
                    int nidx = s + 4; if (nidx > TT - 1) nidx = TT - 1;
                    xp[u] = __ldg(&xp_base[(size_t)nidx * HH]);
                }
                __syncthreads();
            }
        }

        __threadfence();
        __syncthreads();
        if (tid == 0)
            asm volatile("st.release.gpu.global.b32 [%0], %1;"
                         :: "l"(&g_scanflag[b]), "r"(1) : "memory");
    } else if (blockIdx.x < BB + NCHUNK * BB) {
        // ------------------------ xproj role -------------------------
        extern __shared__ float sm[];
        float* xsT = sm;                 // [64][XPAD]
        float* wsT = sm + 64 * XPAD;     // [64][XPAD]
        int f    = blockIdx.x - BB;
        int c    = f >> 7;               // t-chunk (chunk-major order)
        int b    = f & 127;
        int row0 = b * TT + c * 128;     // 128 contiguous (b,t) rows

        if (tid < 256) {
            const float4* xg = (const float4*)(x + (size_t)row0 * DD);
#pragma unroll
            for (int j = 0; j < 8; j++) {
                int idx = tid + 256 * j;
                float4 v = xg[idx];
                int r = idx >> 4, d4 = (idx & 15) << 2;
                xsT[(d4 + 0) * XPAD + r] = v.x;
                xsT[(d4 + 1) * XPAD + r] = v.y;
                xsT[(d4 + 2) * XPAD + r] = v.z;
                xsT[(d4 + 3) * XPAD + r] = v.w;
            }
            const float4* wg = (const float4*)Wih0;
#pragma unroll
            for (int j = 0; j < 8; j++) {
                int idx = tid + 256 * j;
                float4 v = wg[idx];
                int h = idx >> 4, d4 = (idx & 15) << 2;
                wsT[(d4 + 0) * XPAD + h] = v.x;
                wsT[(d4 + 1) * XPAD + h] = v.y;
                wsT[(d4 + 2) * XPAD + h] = v.z;
                wsT[(d4 + 3) * XPAD + h] = v.w;
            }
        }
        __syncthreads();

        if (tid < 256) {
            int tx = tid & 15, ty = tid >> 4;
            int c0 = tx * 8, r0 = ty * 8;
            float acc[8][8];
#pragma unroll
            for (int j = 0; j < 8; j++) {
                float bb = bih0[c0 + j] + bhh0[c0 + j];
#pragma unroll
                for (int i = 0; i < 8; i++) acc[i][j] = bb;
            }
#pragma unroll 8
            for (int k = 0; k < 64; k++) {
                float4 a0 = *(const float4*)&xsT[k * XPAD + r0];
                float4 a1 = *(const float4*)&xsT[k * XPAD + r0 + 4];
                float4 b0 = *(const float4*)&wsT[k * XPAD + c0];
                float4 b1 = *(const float4*)&wsT[k * XPAD + c0 + 4];
                float av[8] = {a0.x, a0.y, a0.z, a0.w, a1.x, a1.y, a1.z, a1.w};
                float bv[8] = {b0.x, b0.y, b0.z, b0.w, b1.x, b1.y, b1.z, b1.w};
#pragma unroll
                for (int i = 0; i < 8; i++)
#pragma unroll
                    for (int j = 0; j < 8; j++)
                        acc[i][j] = fmaf(av[i], bv[j], acc[i][j]);
            }
            float* og = g_xp0 + (size_t)row0 * HH;
#pragma unroll
            for (int i = 0; i < 8; i++) {
                *(float4*)&og[(size_t)(r0 + i) * HH + c0] =
                    make_float4(acc[i][0], acc[i][1], acc[i][2], acc[i][3]);
                *(float4*)&og[(size_t)(r0 + i) * HH + c0 + 4] =
                    make_float4(acc[i][4], acc[i][5], acc[i][6], acc[i][7]);
            }
        }
        __threadfence();
        __syncthreads();
        if (tid == 0)
            asm volatile("st.release.gpu.global.b32 [%0], %1;"
                         :: "l"(&g_xpflag[c * BB + b]), "r"(1) : "memory");
    } else {
        // -------------------------- fc role --------------------------
        __shared__ __align__(16) float wfcT[HH * 33];
        __shared__ __align__(16) float h1s[32 * HH];
        __shared__ float bfcs[OO];

        int f    = blockIdx.x - (BB + NCHUNK * BB);  // 0..8191
        int b    = (BB - 1) - (f >> 6);              // reverse batch order
        int row0 = b * TT + (f & 63) * 32;
        int L    = lengths[b];

        for (int idx = tid; idx < OO * HH; idx += 384) {
            int o = idx >> 7, k = idx & 127;
            wfcT[k * 33 + o] = Wfc[idx];
        }
        if (tid < OO) bfcs[tid] = bfc[tid];

        if (tid == 0) spin_acq(&g_scanflag[b]);
        __syncthreads();   // flag acquired -> h1 visible; smem staged

        const float4* hg = (const float4*)(g_h1 + (size_t)row0 * HH);
        for (int j = tid; j < 1024; j += 384)
            ((float4*)h1s)[j] = hg[j];
        __syncthreads();

        if (tid < 256) {
            int o  = tid & 31;
            int rg = tid >> 5;               // 8 groups x 4 rows
            int tb = row0 % TT;
#pragma unroll
            for (int i = 0; i < 4; i++) {
                int r = rg * 4 + i;
                int t = tb + r;
                float res;
                if (t < L) {
                    float acc = 0.f;
#pragma unroll
                    for (int k = 0; k < HH; k++)
                        acc = fmaf(wfcT[k * 33 + o], h1s[r * HH + k], acc);
                    res = acc + bfcs[o];
                } else {
                    res = bfcs[o];
                }
                out[(size_t)(row0 + r) * OO + o] = res;
            }
        }
    }
}

// ---------------------------------------------------------------------------
extern "C" void kernel_launch(void* const* d_in, const int* in_sizes, int n_in,
                              void* d_out, int out_size) {
    const float* x     = (const float*)d_in[0];
    const int*   len   = (const int*)  d_in[1];
    const float* Wih0  = (const float*)d_in[2];
    const float* Whh0  = (const float*)d_in[3];
    const float* bih0  = (const float*)d_in[4];
    const float* bhh0  = (const float*)d_in[5];
    const float* Wih1  = (const float*)d_in[6];
    const float* Whh1  = (const float*)d_in[7];
    const float* bih1  = (const float*)d_in[8];
    const float* bhh1  = (const float*)d_in[9];
    const float* Wfc   = (const float*)d_in[10];
    const float* bfc   = (const float*)d_in[11];
    float* out = (float*)d_out;

    init_kernel<<<1, 256>>>();

    static_assert(2 * 64 * XPAD * 4 == 67584, "smem size");
    cudaFuncSetAttribute(mega_kernel, cudaFuncAttributeMaxDynamicSharedMemorySize, 67584);
    int grid = BB + NCHUNK * BB + (BB * TT) / 32;   // 128 + 2048 + 8192
    mega_kernel<<<grid, 384, 67584>>>(x, Wih0, bih0, bhh0,
                                      Whh0, Wih1, Whh1, bih1, bhh1, len,
                                      Wfc, bfc, out);
}